// round 4
// baseline (speedup 1.0000x reference)
#include <cuda_runtime.h>
#include <cstdint>
#include <math.h>

#define BB 64
#define TT 512
#define DD 256
#define HH 256
#define KK (DD + HH)   // 512
#define PAD 68         // hx row pitch in floats (16B-aligned, conflict-mitigating)
#define NTHR 256
#define NBLK 128
#define DIRBLK 64      // blocks per direction
#define NBAR (TT + 1)  // barriers per launch per direction

// ---------------- device scratch (static allocation, allowed) ----------------
__device__ float g_xt[2][TT][DD][BB];     // pre-transposed inputs: [dir][t][k][b]  (64 MB)
__device__ float g_hb[2][2][HH][BB];      // double-buffered hidden: [dir][phase][n][b]
__device__ unsigned g_bcnt[2];            // per-direction barrier counters (zero-init)
__device__ unsigned g_bsns[2];            // per-direction barrier sense   (zero-init)

__device__ __forceinline__ float sigf(float v) { return 1.f / (1.f + expf(-v)); }

// Sense-reversal barrier across the 64 blocks of one direction.
// Self-resetting: after the last generation (gen = TT), sense wraps to 0 and
// count is 0, so repeated graph replays see pristine state.
__device__ __forceinline__ void dir_barrier(int dir, unsigned gen) {
    __threadfence();          // every thread's prior global writes -> device visible
    __syncthreads();
    if (threadIdx.x == 0) {
        unsigned arrived = atomicAdd(&g_bcnt[dir], 1u);
        if (arrived == DIRBLK - 1) {
            atomicExch(&g_bcnt[dir], 0u);
            __threadfence();
            atomicExch(&g_bsns[dir], (gen + 1u) % NBAR);
        } else {
            while (*((volatile unsigned*)&g_bsns[dir]) == gen) __nanosleep(64);
        }
        __threadfence();
    }
    __syncthreads();
}

extern "C" __global__ void __launch_bounds__(NTHR, 1)
bilstm_kernel(const float* __restrict__ x,
              const int*   __restrict__ lens,
              const float* __restrict__ Wih_f, const float* __restrict__ Whh_f,
              const float* __restrict__ bih_f, const float* __restrict__ bhh_f,
              const float* __restrict__ Wih_b, const float* __restrict__ Whh_b,
              const float* __restrict__ bih_b, const float* __restrict__ bhh_b,
              float* __restrict__ out)
{
    extern __shared__ float smem[];
    float* hx   = smem;                     // [KK][PAD]  staged [x_t ; h], k-major, b contiguous
    float* wt   = hx + KK * PAD;            // [KK][16]   transposed weight slice (16 rows)
    float* red  = wt + KK * 16;             // [16][3][64] k-split partial sums
    float* bsv  = red + 16 * 3 * 64;        // [16]       bih+bhh for this block's rows
    int*   slen = (int*)(bsv + 16);         // [64]

    const int tid = threadIdx.x;
    const int dir = blockIdx.x >> 6;        // 0 = forward, 1 = backward
    const int nb  = blockIdx.x & 63;        // hidden-dim chunk: n in [4*nb, 4*nb+4)

    const float* Wih = dir ? Wih_b : Wih_f;
    const float* Whh = dir ? Whh_b : Whh_f;
    const float* bih = dir ? bih_b : bih_f;
    const float* bhh = dir ? bhh_b : bhh_f;

    // ---------------- prologue ----------------
    for (int i = tid; i < BB; i += NTHR) slen[i] = lens[i];

    // Weight slice, transposed to [k][r16], r = nl*4 + gate (gate order i,f,g,o)
    for (int idx = tid; idx < KK * 16; idx += NTHR) {
        int k = idx >> 4, r = idx & 15;
        int nl = r >> 2, g = r & 3;
        int j = g * HH + nb * 4 + nl;                   // row in [4H, *] weight
        wt[idx] = (k < DD) ? Wih[(size_t)j * DD + k] : Whh[(size_t)j * HH + (k - DD)];
    }
    if (tid < 16) {
        int nl = tid >> 2, g = tid & 3;
        int j = g * HH + nb * 4 + nl;
        bsv[tid] = bih[j] + bhh[j];
    }
    // zero both h phases for this direction (split across the 64 dir-blocks)
    {
        float* hb = &g_hb[dir][0][0][0];
        const int total = 2 * HH * BB;
        for (int i = nb * NTHR + tid; i < total; i += DIRBLK * NTHR) hb[i] = 0.f;
    }
    __syncthreads();   // slen ready

    // Build pre-transposed x for this direction: xt[s][k][b].
    // Backward uses the reference's inversed index:
    //   t = T-1 - ((T - len[b] + s) % T)
    for (int s = nb; s < TT; s += DIRBLK) {
        float* dst = &g_xt[dir][s][0][0];
        const int k = tid;                 // 0..255 == DD
        for (int b0 = 0; b0 < BB; b0 += 4) {
            int t0, t1, t2, t3;
            if (dir == 0) { t0 = t1 = t2 = t3 = s; }
            else {
                t0 = TT - 1 - ((TT - slen[b0 + 0] + s) % TT);
                t1 = TT - 1 - ((TT - slen[b0 + 1] + s) % TT);
                t2 = TT - 1 - ((TT - slen[b0 + 2] + s) % TT);
                t3 = TT - 1 - ((TT - slen[b0 + 3] + s) % TT);
            }
            float4 v;
            v.x = x[((size_t)(b0 + 0) * TT + t0) * DD + k];
            v.y = x[((size_t)(b0 + 1) * TT + t1) * DD + k];
            v.z = x[((size_t)(b0 + 2) * TT + t2) * DD + k];
            v.w = x[((size_t)(b0 + 3) * TT + t3) * DD + k];
            *(float4*)&dst[k * BB + b0] = v;
        }
    }

    dir_barrier(dir, 0u);

    // ---------------- recurrence ----------------
    // Thread decomposition: kq = K-quarter (0..3), bg = batch group (4 batches),
    // nl = local hidden dim (0..3). Thread tile = 4 gates x 4 batches.
    const int kq = tid >> 6;
    const int r  = tid & 63;
    const int bg = r & 15;
    const int nl = r >> 4;
    const int n  = nb * 4 + nl;

    float creg0 = 0.f, creg1 = 0.f, creg2 = 0.f, creg3 = 0.f;  // cell state (kq==0 threads)
    int p = 0;

    for (int s = 0; s < TT; ++s) {
        // stage [x_s ; h_p] into smem, k-major with batch contiguous
        const float4* xs = (const float4*)&g_xt[dir][s][0][0];  // 256*16 float4
        const float4* hs = (const float4*)&g_hb[dir][p][0][0];  // 256*16 float4
        #pragma unroll 4
        for (int i = tid; i < KK * 16; i += NTHR) {
            int k = i >> 4, c = i & 15;
            float4 v = (k < DD) ? xs[i] : hs[i - DD * 16];
            *(float4*)&hx[k * PAD + c * 4] = v;
        }
        __syncthreads();

        float acc[16];
        #pragma unroll
        for (int i = 0; i < 16; ++i) acc[i] = 0.f;

        const float* hxp = hx + (kq * 128) * PAD + bg * 4;
        const float* wtp = wt + (kq * 128) * 16 + nl * 4;
        #pragma unroll 8
        for (int kk = 0; kk < 128; ++kk) {
            float4 h4 = *(const float4*)(hxp + kk * PAD);   // 4 batches at this k
            float4 w4 = *(const float4*)(wtp + kk * 16);    // 4 gates   at this k
            acc[0]  += w4.x * h4.x; acc[1]  += w4.x * h4.y; acc[2]  += w4.x * h4.z; acc[3]  += w4.x * h4.w;
            acc[4]  += w4.y * h4.x; acc[5]  += w4.y * h4.y; acc[6]  += w4.y * h4.z; acc[7]  += w4.y * h4.w;
            acc[8]  += w4.z * h4.x; acc[9]  += w4.z * h4.y; acc[10] += w4.z * h4.z; acc[11] += w4.z * h4.w;
            acc[12] += w4.w * h4.x; acc[13] += w4.w * h4.y; acc[14] += w4.w * h4.z; acc[15] += w4.w * h4.w;
        }

        // reduce the 4 K-quarters: kq!=0 publish, kq==0 accumulate
        if (kq) {
            #pragma unroll
            for (int i = 0; i < 16; ++i)
                red[i * 192 + (kq - 1) * 64 + r] = acc[i];
        }
        __syncthreads();

        if (kq == 0) {
            #pragma unroll
            for (int i = 0; i < 16; ++i)
                acc[i] += red[i * 192 + r] + red[i * 192 + 64 + r] + red[i * 192 + 128 + r];

            const float b0v = bsv[nl * 4 + 0];
            const float b1v = bsv[nl * 4 + 1];
            const float b2v = bsv[nl * 4 + 2];
            const float b3v = bsv[nl * 4 + 3];

            float4 hv;
            float* hvp = &hv.x;
            #pragma unroll
            for (int bi = 0; bi < 4; ++bi) {
                float pi = acc[0  + bi] + b0v;
                float pf = acc[4  + bi] + b1v;
                float pg = acc[8  + bi] + b2v;
                float po = acc[12 + bi] + b3v;
                float cprev = (bi == 0) ? creg0 : (bi == 1) ? creg1 : (bi == 2) ? creg2 : creg3;
                float cnew  = sigf(pf) * cprev + sigf(pi) * tanhf(pg);
                float hval  = sigf(po) * tanhf(cnew);
                if      (bi == 0) creg0 = cnew;
                else if (bi == 1) creg1 = cnew;
                else if (bi == 2) creg2 = cnew;
                else              creg3 = cnew;
                hvp[bi] = hval;

                const int b = bg * 4 + bi;
                const int L = slen[b];
                if (s < L) {
                    const int t = dir ? (L - 1 - s) : s;   // bwd states land re-reversed
                    out[((size_t)b * TT + t) * (2 * HH) + dir * HH + n] = hval;
                }
            }
            *(float4*)&g_hb[dir][p ^ 1][n][bg * 4] = hv;
        }

        dir_barrier(dir, (unsigned)(s + 1));
        p ^= 1;
    }
}

extern "C" void kernel_launch(void* const* d_in, const int* in_sizes, int n_in,
                              void* d_out, int out_size) {
    const float* x     = (const float*)d_in[0];
    const int*   lens  = (const int*)  d_in[1];
    const float* Wih_f = (const float*)d_in[2];
    const float* Whh_f = (const float*)d_in[3];
    const float* bih_f = (const float*)d_in[4];
    const float* bhh_f = (const float*)d_in[5];
    const float* Wih_b = (const float*)d_in[6];
    const float* Whh_b = (const float*)d_in[7];
    const float* bih_b = (const float*)d_in[8];
    const float* bhh_b = (const float*)d_in[9];
    float* out = (float*)d_out;

    // zero the padded/masked region (output beyond input_length must be 0)
    cudaMemsetAsync(out, 0, (size_t)out_size * sizeof(float), 0);

    const size_t smem_bytes =
        (size_t)(KK * PAD + KK * 16 + 16 * 3 * 64 + 16) * sizeof(float) + BB * sizeof(int);
    cudaFuncSetAttribute(bilstm_kernel,
                         cudaFuncAttributeMaxDynamicSharedMemorySize, (int)smem_bytes);

    bilstm_kernel<<<NBLK, NTHR, smem_bytes>>>(x, lens, Wih_f, Whh_f, bih_f, bhh_f,
                                              Wih_b, Whh_b, bih_b, bhh_b, out);
}

// round 5
// speedup vs baseline: 1.0281x; 1.0281x over previous
#include <cuda_runtime.h>
#include <cstdint>
#include <math.h>

#define BB 64
#define TT 512
#define DD 256
#define HH 256
#define KK (DD + HH)   // 512
#define PAD 68         // hx row pitch in floats (16B-aligned, conflict-mitigating)
#define NTHR 256
#define NBLK 128
#define DIRBLK 64      // blocks per direction
#define NBAR (TT + 1)  // barriers per launch per direction

// ---------------- device scratch (static allocation, allowed) ----------------
__device__ float g_xt[2][TT][DD][BB];     // pre-transposed inputs: [dir][t][k][b]  (64 MB)
__device__ float g_hb[2][2][HH][BB];      // double-buffered hidden: [dir][phase][n][b]
__device__ unsigned g_bcnt[2];            // per-direction barrier counters (zero-init)
__device__ unsigned g_bsns[2];            // per-direction barrier sense   (zero-init)

__device__ __forceinline__ float sigf(float v) { return 1.f / (1.f + expf(-v)); }

// Sense-reversal barrier across the 64 blocks of one direction.
// Self-resetting: after the last generation (gen = TT), sense wraps to 0 and
// count is 0, so repeated graph replays see pristine state.
__device__ __forceinline__ void dir_barrier(int dir, unsigned gen) {
    __threadfence();          // every thread's prior global writes -> device visible
    __syncthreads();
    if (threadIdx.x == 0) {
        unsigned arrived = atomicAdd(&g_bcnt[dir], 1u);
        if (arrived == DIRBLK - 1) {
            atomicExch(&g_bcnt[dir], 0u);
            __threadfence();
            atomicExch(&g_bsns[dir], (gen + 1u) % NBAR);
        } else {
            while (*((volatile unsigned*)&g_bsns[dir]) == gen) __nanosleep(64);
        }
        __threadfence();
    }
    __syncthreads();
}

extern "C" __global__ void __launch_bounds__(NTHR, 1)
bilstm_kernel(const float* __restrict__ x,
              const int*   __restrict__ lens,
              const float* __restrict__ Wih_f, const float* __restrict__ Whh_f,
              const float* __restrict__ bih_f, const float* __restrict__ bhh_f,
              const float* __restrict__ Wih_b, const float* __restrict__ Whh_b,
              const float* __restrict__ bih_b, const float* __restrict__ bhh_b,
              float* __restrict__ out)
{
    extern __shared__ float smem[];
    float* hx   = smem;                     // [KK][PAD]  staged [x_t ; h], k-major, b contiguous
    float* wt   = hx + KK * PAD;            // [KK][16]   transposed weight slice (16 rows)
    float* red  = wt + KK * 16;             // [16][3][64] k-split partial sums
    float* bsv  = red + 16 * 3 * 64;        // [16]       bih+bhh for this block's rows
    int*   slen = (int*)(bsv + 16);         // [64]

    const int tid = threadIdx.x;
    const int dir = blockIdx.x >> 6;        // 0 = forward, 1 = backward
    const int nb  = blockIdx.x & 63;        // hidden-dim chunk: n in [4*nb, 4*nb+4)

    const float* Wih = dir ? Wih_b : Wih_f;
    const float* Whh = dir ? Whh_b : Whh_f;
    const float* bih = dir ? bih_b : bih_f;
    const float* bhh = dir ? bhh_b : bhh_f;

    // ---------------- prologue ----------------
    for (int i = tid; i < BB; i += NTHR) slen[i] = lens[i];

    // Weight slice, transposed to [k][r16], r = nl*4 + gate (gate order i,f,g,o)
    for (int idx = tid; idx < KK * 16; idx += NTHR) {
        int k = idx >> 4, r = idx & 15;
        int nl = r >> 2, g = r & 3;
        int j = g * HH + nb * 4 + nl;                   // row in [4H, *] weight
        wt[idx] = (k < DD) ? Wih[(size_t)j * DD + k] : Whh[(size_t)j * HH + (k - DD)];
    }
    if (tid < 16) {
        int nl = tid >> 2, g = tid & 3;
        int j = g * HH + nb * 4 + nl;
        bsv[tid] = bih[j] + bhh[j];
    }
    // zero both h phases for this direction (split across the 64 dir-blocks)
    {
        float* hb = &g_hb[dir][0][0][0];
        const int total = 2 * HH * BB;
        for (int i = nb * NTHR + tid; i < total; i += DIRBLK * NTHR) hb[i] = 0.f;
    }
    __syncthreads();   // slen ready

    // Build pre-transposed x for this direction: xt[s][k][b].
    // Backward uses the reference's inversed index:
    //   t = T-1 - ((T - len[b] + s) % T)
    for (int s = nb; s < TT; s += DIRBLK) {
        float* dst = &g_xt[dir][s][0][0];
        const int k = tid;                 // 0..255 == DD
        for (int b0 = 0; b0 < BB; b0 += 4) {
            int t0, t1, t2, t3;
            if (dir == 0) { t0 = t1 = t2 = t3 = s; }
            else {
                t0 = TT - 1 - ((TT - slen[b0 + 0] + s) % TT);
                t1 = TT - 1 - ((TT - slen[b0 + 1] + s) % TT);
                t2 = TT - 1 - ((TT - slen[b0 + 2] + s) % TT);
                t3 = TT - 1 - ((TT - slen[b0 + 3] + s) % TT);
            }
            float4 v;
            v.x = x[((size_t)(b0 + 0) * TT + t0) * DD + k];
            v.y = x[((size_t)(b0 + 1) * TT + t1) * DD + k];
            v.z = x[((size_t)(b0 + 2) * TT + t2) * DD + k];
            v.w = x[((size_t)(b0 + 3) * TT + t3) * DD + k];
            *(float4*)&dst[k * BB + b0] = v;
        }
    }

    dir_barrier(dir, 0u);

    // ---------------- recurrence ----------------
    // Thread decomposition: kq = K-quarter (0..3), bg = batch group (4 batches),
    // nl = local hidden dim (0..3). Thread tile = 4 gates x 4 batches.
    const int kq = tid >> 6;
    const int r  = tid & 63;
    const int bg = r & 15;
    const int nl = r >> 4;
    const int n  = nb * 4 + nl;

    float creg0 = 0.f, creg1 = 0.f, creg2 = 0.f, creg3 = 0.f;  // cell state (kq==0 threads)
    int p = 0;

    for (int s = 0; s < TT; ++s) {
        // stage [x_s ; h_p] into smem, k-major with batch contiguous
        const float4* xs = (const float4*)&g_xt[dir][s][0][0];  // 256*16 float4
        const float4* hs = (const float4*)&g_hb[dir][p][0][0];  // 256*16 float4
        #pragma unroll 4
        for (int i = tid; i < KK * 16; i += NTHR) {
            int k = i >> 4, c = i & 15;
            float4 v = (k < DD) ? xs[i] : hs[i - DD * 16];
            *(float4*)&hx[k * PAD + c * 4] = v;
        }
        __syncthreads();

        float acc[16];
        #pragma unroll
        for (int i = 0; i < 16; ++i) acc[i] = 0.f;

        const float* hxp = hx + (kq * 128) * PAD + bg * 4;
        const float* wtp = wt + (kq * 128) * 16 + nl * 4;
        #pragma unroll 8
        for (int kk = 0; kk < 128; ++kk) {
            float4 h4 = *(const float4*)(hxp + kk * PAD);   // 4 batches at this k
            float4 w4 = *(const float4*)(wtp + kk * 16);    // 4 gates   at this k
            acc[0]  += w4.x * h4.x; acc[1]  += w4.x * h4.y; acc[2]  += w4.x * h4.z; acc[3]  += w4.x * h4.w;
            acc[4]  += w4.y * h4.x; acc[5]  += w4.y * h4.y; acc[6]  += w4.y * h4.z; acc[7]  += w4.y * h4.w;
            acc[8]  += w4.z * h4.x; acc[9]  += w4.z * h4.y; acc[10] += w4.z * h4.z; acc[11] += w4.z * h4.w;
            acc[12] += w4.w * h4.x; acc[13] += w4.w * h4.y; acc[14] += w4.w * h4.z; acc[15] += w4.w * h4.w;
        }

        // reduce the 4 K-quarters: kq!=0 publish, kq==0 accumulate
        if (kq) {
            #pragma unroll
            for (int i = 0; i < 16; ++i)
                red[i * 192 + (kq - 1) * 64 + r] = acc[i];
        }
        __syncthreads();

        if (kq == 0) {
            #pragma unroll
            for (int i = 0; i < 16; ++i)
                acc[i] += red[i * 192 + r] + red[i * 192 + 64 + r] + red[i * 192 + 128 + r];

            const float b0v = bsv[nl * 4 + 0];
            const float b1v = bsv[nl * 4 + 1];
            const float b2v = bsv[nl * 4 + 2];
            const float b3v = bsv[nl * 4 + 3];

            float4 hv;
            float* hvp = &hv.x;
            #pragma unroll
            for (int bi = 0; bi < 4; ++bi) {
                float pi = acc[0  + bi] + b0v;
                float pf = acc[4  + bi] + b1v;
                float pg = acc[8  + bi] + b2v;
                float po = acc[12 + bi] + b3v;
                float cprev = (bi == 0) ? creg0 : (bi == 1) ? creg1 : (bi == 2) ? creg2 : creg3;
                float cnew  = sigf(pf) * cprev + sigf(pi) * tanhf(pg);
                float hval  = sigf(po) * tanhf(cnew);
                if      (bi == 0) creg0 = cnew;
                else if (bi == 1) creg1 = cnew;
                else if (bi == 2) creg2 = cnew;
                else              creg3 = cnew;
                hvp[bi] = hval;

                const int b = bg * 4 + bi;
                const int L = slen[b];
                if (s < L) {
                    const int t = dir ? (L - 1 - s) : s;   // bwd states land re-reversed
                    out[((size_t)b * TT + t) * (2 * HH) + dir * HH + n] = hval;
                }
            }
            *(float4*)&g_hb[dir][p ^ 1][n][bg * 4] = hv;
        }

        dir_barrier(dir, (unsigned)(s + 1));
        p ^= 1;
    }
}

extern "C" void kernel_launch(void* const* d_in, const int* in_sizes, int n_in,
                              void* d_out, int out_size) {
    const float* x     = (const float*)d_in[0];
    const int*   lens  = (const int*)  d_in[1];
    const float* Wih_f = (const float*)d_in[2];
    const float* Whh_f = (const float*)d_in[3];
    const float* bih_f = (const float*)d_in[4];
    const float* bhh_f = (const float*)d_in[5];
    const float* Wih_b = (const float*)d_in[6];
    const float* Whh_b = (const float*)d_in[7];
    const float* bih_b = (const float*)d_in[8];
    const float* bhh_b = (const float*)d_in[9];
    float* out = (float*)d_out;

    // zero the padded/masked region (output beyond input_length must be 0)
    cudaMemsetAsync(out, 0, (size_t)out_size * sizeof(float), 0);

    const size_t smem_bytes =
        (size_t)(KK * PAD + KK * 16 + 16 * 3 * 64 + 16) * sizeof(float) + BB * sizeof(int);
    cudaFuncSetAttribute(bilstm_kernel,
                         cudaFuncAttributeMaxDynamicSharedMemorySize, (int)smem_bytes);

    bilstm_kernel<<<NBLK, NTHR, smem_bytes>>>(x, lens, Wih_f, Whh_f, bih_f, bhh_f,
                                              Wih_b, Whh_b, bih_b, bhh_b, out);
}

// round 6
// speedup vs baseline: 1.0737x; 1.0443x over previous
#include <cuda_runtime.h>
#include <cstdint>
#include <math.h>

#define BB 64
#define TT 512
#define DD 256
#define HH 256
#define KK (DD + HH)   // 512
#define PAD 68         // hx row pitch in floats (16B-aligned, conflict-mitigating)
#define NTHR 256
#define NBLK 128
#define DIRBLK 64      // blocks per direction
#define NBAR (TT + 1)  // barriers per launch per direction

// ---------------- device scratch (static allocation, allowed) ----------------
__device__ float g_xt[2][TT][DD][BB];     // pre-transposed inputs: [dir][t][k][b]  (64 MB)
__device__ float g_hb[2][2][HH][BB];      // double-buffered hidden: [dir][phase][n][b]
__device__ unsigned g_bcnt[2];            // per-direction barrier counters (zero-init)
__device__ unsigned g_bsns[2];            // per-direction barrier sense   (zero-init)

__device__ __forceinline__ float sigf(float v) { return 1.f / (1.f + expf(-v)); }

// ---- packed fp32x2 helpers (sm_100+) ----
__device__ __forceinline__ void fmaf2(unsigned long long& d,
                                      unsigned long long a, unsigned long long b) {
    asm("fma.rn.f32x2 %0, %1, %2, %3;" : "=l"(d) : "l"(a), "l"(b), "l"(d));
}
__device__ __forceinline__ unsigned long long addf2(unsigned long long a,
                                                    unsigned long long b) {
    unsigned long long r;
    asm("add.rn.f32x2 %0, %1, %2;" : "=l"(r) : "l"(a), "l"(b));
    return r;
}
__device__ __forceinline__ void unpack2(unsigned long long v, float& lo, float& hi) {
    asm("mov.b64 {%0, %1}, %2;" : "=f"(lo), "=f"(hi) : "l"(v));
}

// ---- cp.async helpers ----
__device__ __forceinline__ void cpa16(uint32_t dst_smem, const void* src) {
    asm volatile("cp.async.cg.shared.global [%0], [%1], 16;"
                 :: "r"(dst_smem), "l"(src));
}
#define CP_COMMIT() asm volatile("cp.async.commit_group;")
#define CP_WAIT0()  asm volatile("cp.async.wait_group 0;")

__device__ __forceinline__ uint32_t smem_u32(const void* p) {
    uint32_t a;
    asm("{ .reg .u64 t; cvta.to.shared.u64 t, %1; cvt.u32.u64 %0, t; }"
        : "=r"(a) : "l"(p));
    return a;
}

// Sense-reversal barrier across the 64 blocks of one direction.
// Self-resetting: after gen = TT the sense wraps to 0 and count is 0, so
// repeated graph replays see pristine state.
__device__ __forceinline__ void dir_barrier(int dir, unsigned gen) {
    __threadfence();
    __syncthreads();
    if (threadIdx.x == 0) {
        unsigned arrived = atomicAdd(&g_bcnt[dir], 1u);
        if (arrived == DIRBLK - 1) {
            atomicExch(&g_bcnt[dir], 0u);
            __threadfence();
            atomicExch(&g_bsns[dir], (gen + 1u) % NBAR);
        } else {
            while (*((volatile unsigned*)&g_bsns[dir]) == gen) __nanosleep(64);
        }
        __threadfence();
    }
    __syncthreads();
}

extern "C" __global__ void __launch_bounds__(NTHR, 1)
bilstm_kernel(const float* __restrict__ x,
              const int*   __restrict__ lens,
              const float* __restrict__ Wih_f, const float* __restrict__ Whh_f,
              const float* __restrict__ bih_f, const float* __restrict__ bhh_f,
              const float* __restrict__ Wih_b, const float* __restrict__ Whh_b,
              const float* __restrict__ bih_b, const float* __restrict__ bhh_b,
              float* __restrict__ out)
{
    extern __shared__ float smem[];
    float* hx   = smem;                     // [KK][PAD] staged [x_t ; h], k-major
    float* wt2  = hx + KK * PAD;            // [KK][32]  duplicated-pair weights
    float* redf = wt2 + KK * 32;            // [8][3][64] u64 k-split partials (12KB)
    float* bsv  = redf + 8 * 3 * 64 * 2;    // [16] bih+bhh
    int*   slen = (int*)(bsv + 16);         // [64]
    unsigned long long* redu = (unsigned long long*)redf;

    const uint32_t hx_base = smem_u32(hx);

    const int tid = threadIdx.x;
    const int dir = blockIdx.x >> 6;        // 0 = forward, 1 = backward
    const int nb  = blockIdx.x & 63;        // hidden chunk: n in [4*nb, 4*nb+4)

    const float* Wih = dir ? Wih_b : Wih_f;
    const float* Whh = dir ? Whh_b : Whh_f;
    const float* bih = dir ? bih_b : bih_f;
    const float* bhh = dir ? bhh_b : bhh_f;

    // ---------------- prologue ----------------
    for (int i = tid; i < BB; i += NTHR) slen[i] = lens[i];

    // Weight slice, duplicated pairs: wt2[k][nl*8 + g*2 + {0,1}] = w  (r = nl*4+g)
    for (int idx = tid; idx < KK * 16; idx += NTHR) {
        int k = idx >> 4, r = idx & 15;
        int nl = r >> 2, g = r & 3;
        int j = g * HH + nb * 4 + nl;
        float w = (k < DD) ? Wih[(size_t)j * DD + k] : Whh[(size_t)j * HH + (k - DD)];
        wt2[k * 32 + r * 2 + 0] = w;
        wt2[k * 32 + r * 2 + 1] = w;
    }
    if (tid < 16) {
        int nl = tid >> 2, g = tid & 3;
        int j = g * HH + nb * 4 + nl;
        bsv[tid] = bih[j] + bhh[j];
    }
    {   // zero both h phases for this direction
        float* hb = &g_hb[dir][0][0][0];
        const int total = 2 * HH * BB;
        for (int i = nb * NTHR + tid; i < total; i += DIRBLK * NTHR) hb[i] = 0.f;
    }
    __syncthreads();   // slen ready

    // Build pre-transposed x for this direction: xt[s][k][b].
    for (int s = nb; s < TT; s += DIRBLK) {
        float* dst = &g_xt[dir][s][0][0];
        const int k = tid;
        for (int b0 = 0; b0 < BB; b0 += 4) {
            int t0, t1, t2, t3;
            if (dir == 0) { t0 = t1 = t2 = t3 = s; }
            else {
                t0 = TT - 1 - ((TT - slen[b0 + 0] + s) % TT);
                t1 = TT - 1 - ((TT - slen[b0 + 1] + s) % TT);
                t2 = TT - 1 - ((TT - slen[b0 + 2] + s) % TT);
                t3 = TT - 1 - ((TT - slen[b0 + 3] + s) % TT);
            }
            float4 v;
            v.x = x[((size_t)(b0 + 0) * TT + t0) * DD + k];
            v.y = x[((size_t)(b0 + 1) * TT + t1) * DD + k];
            v.z = x[((size_t)(b0 + 2) * TT + t2) * DD + k];
            v.w = x[((size_t)(b0 + 3) * TT + t3) * DD + k];
            *(float4*)&dst[k * BB + b0] = v;
        }
    }

    dir_barrier(dir, 0u);

    // Prefetch x(0) into the x-half of hx (drained by step 0's wait).
    {
        const char* xsrc = (const char*)&g_xt[dir][0][0][0];
        #pragma unroll
        for (int j = 0; j < 16; ++j) {
            int i = tid + j * NTHR;            // 0..4095
            int k = i >> 4, c = i & 15;
            cpa16(hx_base + (uint32_t)((k * PAD + c * 4) * 4), xsrc + (size_t)i * 16);
        }
        CP_COMMIT();
    }

    // ---------------- recurrence ----------------
    const int kq = tid >> 6;       // K-quarter (0..3)
    const int r  = tid & 63;
    const int bg = r & 15;         // batch group (4 batches)
    const int nl = r >> 4;         // local hidden dim (0..3)
    const int n  = nb * 4 + nl;

    float creg0 = 0.f, creg1 = 0.f, creg2 = 0.f, creg3 = 0.f;
    int p = 0;

    for (int s = 0; s < TT; ++s) {
        // stage h_p into smem rows [DD..KK) via cp.async; wait also drains the
        // x(s) prefetch group committed last iteration.
        {
            const char* hsrc = (const char*)&g_hb[dir][p][0][0];
            #pragma unroll
            for (int j = 0; j < 16; ++j) {
                int i = tid + j * NTHR;
                int k = i >> 4, c = i & 15;
                cpa16(hx_base + (uint32_t)(((DD + k) * PAD + c * 4) * 4),
                      hsrc + (size_t)i * 16);
            }
            CP_COMMIT();
            CP_WAIT0();
        }
        __syncthreads();

        unsigned long long acc2[8];    // acc2[g*2+bp]: gate g, batch-pair bp
        #pragma unroll
        for (int i = 0; i < 8; ++i) acc2[i] = 0ull;

        const float* hxp = hx  + (kq * 128) * PAD + bg * 4;
        const float* wtp = wt2 + (kq * 128) * 32  + nl * 8;
        #pragma unroll 8
        for (int kk = 0; kk < 128; ++kk) {
            ulonglong2 h2  = *(const ulonglong2*)(hxp + kk * PAD);      // (b0,b1),(b2,b3)
            ulonglong2 w01 = *(const ulonglong2*)(wtp + kk * 32);       // (g0,g0),(g1,g1)
            ulonglong2 w23 = *(const ulonglong2*)(wtp + kk * 32 + 4);   // (g2,g2),(g3,g3)
            fmaf2(acc2[0], w01.x, h2.x); fmaf2(acc2[1], w01.x, h2.y);
            fmaf2(acc2[2], w01.y, h2.x); fmaf2(acc2[3], w01.y, h2.y);
            fmaf2(acc2[4], w23.x, h2.x); fmaf2(acc2[5], w23.x, h2.y);
            fmaf2(acc2[6], w23.y, h2.x); fmaf2(acc2[7], w23.y, h2.y);
        }

        // publish k-split partials (packed)
        if (kq) {
            #pragma unroll
            for (int i = 0; i < 8; ++i)
                redu[i * 192 + (kq - 1) * 64 + r] = acc2[i];
        }
        __syncthreads();   // all warps done with FFMA + x region of hx

        // prefetch x(s+1) into the (now idle) x-half; overlaps epilogue+barrier
        if (s + 1 < TT) {
            const char* xsrc = (const char*)&g_xt[dir][s + 1][0][0];
            #pragma unroll
            for (int j = 0; j < 16; ++j) {
                int i = tid + j * NTHR;
                int k = i >> 4, c = i & 15;
                cpa16(hx_base + (uint32_t)((k * PAD + c * 4) * 4), xsrc + (size_t)i * 16);
            }
            CP_COMMIT();
        }

        if (kq == 0) {
            float accf[16];   // accf[g*4 + bi]
            #pragma unroll
            for (int i = 0; i < 8; ++i) {
                unsigned long long v =
                    addf2(addf2(acc2[i], redu[i * 192 + r]),
                          addf2(redu[i * 192 + 64 + r], redu[i * 192 + 128 + r]));
                int g = i >> 1, bp = i & 1;
                unpack2(v, accf[g * 4 + bp * 2], accf[g * 4 + bp * 2 + 1]);
            }

            const float b0v = bsv[nl * 4 + 0];
            const float b1v = bsv[nl * 4 + 1];
            const float b2v = bsv[nl * 4 + 2];
            const float b3v = bsv[nl * 4 + 3];

            float4 hv;
            float* hvp = &hv.x;
            #pragma unroll
            for (int bi = 0; bi < 4; ++bi) {
                float pi = accf[0  + bi] + b0v;
                float pf = accf[4  + bi] + b1v;
                float pg = accf[8  + bi] + b2v;
                float po = accf[12 + bi] + b3v;
                float cprev = (bi == 0) ? creg0 : (bi == 1) ? creg1 : (bi == 2) ? creg2 : creg3;
                float cnew  = sigf(pf) * cprev + sigf(pi) * tanhf(pg);
                float hval  = sigf(po) * tanhf(cnew);
                if      (bi == 0) creg0 = cnew;
                else if (bi == 1) creg1 = cnew;
                else if (bi == 2) creg2 = cnew;
                else              creg3 = cnew;
                hvp[bi] = hval;

                const int b = bg * 4 + bi;
                const int L = slen[b];
                if (s < L) {
                    const int t = dir ? (L - 1 - s) : s;
                    out[((size_t)b * TT + t) * (2 * HH) + dir * HH + n] = hval;
                }
            }
            *(float4*)&g_hb[dir][p ^ 1][n][bg * 4] = hv;
        }

        dir_barrier(dir, (unsigned)(s + 1));
        p ^= 1;
    }
}

extern "C" void kernel_launch(void* const* d_in, const int* in_sizes, int n_in,
                              void* d_out, int out_size) {
    const float* x     = (const float*)d_in[0];
    const int*   lens  = (const int*)  d_in[1];
    const float* Wih_f = (const float*)d_in[2];
    const float* Whh_f = (const float*)d_in[3];
    const float* bih_f = (const float*)d_in[4];
    const float* bhh_f = (const float*)d_in[5];
    const float* Wih_b = (const float*)d_in[6];
    const float* Whh_b = (const float*)d_in[7];
    const float* bih_b = (const float*)d_in[8];
    const float* bhh_b = (const float*)d_in[9];
    float* out = (float*)d_out;

    // zero the padded/masked region (output beyond input_length must be 0)
    cudaMemsetAsync(out, 0, (size_t)out_size * sizeof(float), 0);

    const size_t smem_bytes =
        (size_t)(KK * PAD + KK * 32 + 8 * 3 * 64 * 2 + 16) * sizeof(float)
        + BB * sizeof(int);
    cudaFuncSetAttribute(bilstm_kernel,
                         cudaFuncAttributeMaxDynamicSharedMemorySize, (int)smem_bytes);

    bilstm_kernel<<<NBLK, NTHR, smem_bytes>>>(x, lens, Wih_f, Whh_f, bih_f, bhh_f,
                                              Wih_b, Whh_b, bih_b, bhh_b, out);
}

// round 7
// speedup vs baseline: 1.2873x; 1.1990x over previous
#include <cuda_runtime.h>
#include <cstdint>
#include <math.h>

#define BB 64
#define TT 512
#define DD 256
#define HH 256
#define KK (DD + HH)   // 512
#define PAD 68         // hx row pitch in floats (16B-aligned, conflict-mitigating)
#define NTHR 256
#define NBLK 128
#define DIRBLK 64      // blocks per direction

// ---------------- device scratch (static allocation, allowed) ----------------
__device__ float g_xt[2][TT][DD][BB];     // pre-transposed inputs: [dir][t][k][b]  (64 MB)
__device__ float g_hb[2][2][HH][BB];      // double-buffered hidden: [dir][phase][n][b]
__device__ int   g_flag[2][DIRBLK];       // per-block step flags (reset to 0 at launch end)
__device__ unsigned g_bcnt[2];            // final-barrier counter (self-resetting)
__device__ unsigned g_bsns[2];            // final-barrier sense (local-sense, launch-stable)

// ---- fast gate math (|rel err| ~1e-6, saturation-safe) ----
__device__ __forceinline__ float fsig(float v) {
    return __fdividef(1.f, 1.f + __expf(-v));
}
__device__ __forceinline__ float ftanh(float v) {
    return 1.f - __fdividef(2.f, __expf(2.f * v) + 1.f);
}

// ---- packed fp32x2 helpers (sm_100+) ----
__device__ __forceinline__ void fmaf2(unsigned long long& d,
                                      unsigned long long a, unsigned long long b) {
    asm("fma.rn.f32x2 %0, %1, %2, %3;" : "=l"(d) : "l"(a), "l"(b), "l"(d));
}
__device__ __forceinline__ void unpack2(unsigned long long v, float& lo, float& hi) {
    asm("mov.b64 {%0, %1}, %2;" : "=f"(lo), "=f"(hi) : "l"(v));
}

// ---- cp.async helpers ----
__device__ __forceinline__ void cpa16(uint32_t dst_smem, const void* src) {
    asm volatile("cp.async.cg.shared.global [%0], [%1], 16;"
                 :: "r"(dst_smem), "l"(src));
}
#define CP_COMMIT() asm volatile("cp.async.commit_group;")
#define CP_WAIT0()  asm volatile("cp.async.wait_group 0;")

__device__ __forceinline__ uint32_t smem_u32(const void* p) {
    uint32_t a;
    asm("{ .reg .u64 t; cvta.to.shared.u64 t, %1; cvt.u32.u64 %0, t; }"
        : "=r"(a) : "l"(p));
    return a;
}

// Inner GEMM phase: 64 k-steps, 16 MACs/k via 8 FFMA2.
__device__ __forceinline__ void gemm_phase(unsigned long long* acc2,
                                           const float* __restrict__ hxp,
                                           const float* __restrict__ wtp) {
    #pragma unroll 8
    for (int kk = 0; kk < 64; ++kk) {
        ulonglong2 h2  = *(const ulonglong2*)(hxp + kk * PAD);      // (b0,b1),(b2,b3)
        ulonglong2 w01 = *(const ulonglong2*)(wtp + kk * 32);       // (g0,g0),(g1,g1)
        ulonglong2 w23 = *(const ulonglong2*)(wtp + kk * 32 + 4);   // (g2,g2),(g3,g3)
        fmaf2(acc2[0], w01.x, h2.x); fmaf2(acc2[1], w01.x, h2.y);
        fmaf2(acc2[2], w01.y, h2.x); fmaf2(acc2[3], w01.y, h2.y);
        fmaf2(acc2[4], w23.x, h2.x); fmaf2(acc2[5], w23.x, h2.y);
        fmaf2(acc2[6], w23.y, h2.x); fmaf2(acc2[7], w23.y, h2.y);
    }
}

extern "C" __global__ void __launch_bounds__(NTHR, 1)
bilstm_kernel(const float* __restrict__ x,
              const int*   __restrict__ lens,
              const float* __restrict__ Wih_f, const float* __restrict__ Whh_f,
              const float* __restrict__ bih_f, const float* __restrict__ bhh_f,
              const float* __restrict__ Wih_b, const float* __restrict__ Whh_b,
              const float* __restrict__ bih_b, const float* __restrict__ bhh_b,
              float* __restrict__ out)
{
    extern __shared__ float smem[];
    float* hx   = smem;                     // [KK][PAD] staged [x_t ; h], k-major
    float* wt2  = hx + KK * PAD;            // [KK][32]  duplicated-pair weights
    float* red  = wt2 + KK * 32;            // [4][16][64] unpacked k-split partials
    float* bsv  = red + 4 * 16 * 64;        // [16] bih+bhh
    int*   slen = (int*)(bsv + 16);         // [64]

    const uint32_t hx_base = smem_u32(hx);

    const int tid = threadIdx.x;
    const int dir = blockIdx.x >> 6;        // 0 = forward, 1 = backward
    const int nb  = blockIdx.x & 63;        // hidden chunk: n in [4*nb, 4*nb+4)

    const float* Wih = dir ? Wih_b : Wih_f;
    const float* Whh = dir ? Whh_b : Whh_f;
    const float* bih = dir ? bih_b : bih_f;
    const float* bhh = dir ? bhh_b : bhh_f;

    // ---------------- prologue ----------------
    for (int i = tid; i < BB; i += NTHR) slen[i] = lens[i];

    // Weight slice, duplicated pairs: wt2[k][r*2 + {0,1}], r = nl*4+g
    for (int idx = tid; idx < KK * 16; idx += NTHR) {
        int k = idx >> 4, r = idx & 15;
        int nl = r >> 2, g = r & 3;
        int j = g * HH + nb * 4 + nl;
        float w = (k < DD) ? Wih[(size_t)j * DD + k] : Whh[(size_t)j * HH + (k - DD)];
        wt2[k * 32 + r * 2 + 0] = w;
        wt2[k * 32 + r * 2 + 1] = w;
    }
    if (tid < 16) {
        int nl = tid >> 2, g = tid & 3;
        int j = g * HH + nb * 4 + nl;
        bsv[tid] = bih[j] + bhh[j];
    }
    {   // zero both h phases for this direction
        float* hb = &g_hb[dir][0][0][0];
        const int total = 2 * HH * BB;
        for (int i = nb * NTHR + tid; i < total; i += DIRBLK * NTHR) hb[i] = 0.f;
    }
    __syncthreads();   // slen ready

    // Build pre-transposed x for this direction: xt[s][k][b].
    for (int s = nb; s < TT; s += DIRBLK) {
        float* dst = &g_xt[dir][s][0][0];
        const int k = tid;
        for (int b0 = 0; b0 < BB; b0 += 4) {
            int t0, t1, t2, t3;
            if (dir == 0) { t0 = t1 = t2 = t3 = s; }
            else {
                t0 = TT - 1 - ((TT - slen[b0 + 0] + s) % TT);
                t1 = TT - 1 - ((TT - slen[b0 + 1] + s) % TT);
                t2 = TT - 1 - ((TT - slen[b0 + 2] + s) % TT);
                t3 = TT - 1 - ((TT - slen[b0 + 3] + s) % TT);
            }
            float4 v;
            v.x = x[((size_t)(b0 + 0) * TT + t0) * DD + k];
            v.y = x[((size_t)(b0 + 1) * TT + t1) * DD + k];
            v.z = x[((size_t)(b0 + 2) * TT + t2) * DD + k];
            v.w = x[((size_t)(b0 + 3) * TT + t3) * DD + k];
            *(float4*)&dst[k * BB + b0] = v;
        }
    }
    __syncthreads();

    // Post prologue-done flag (value 1), then wait for all blocks of this dir.
    if (tid == 0) {
        __threadfence();
        *((volatile int*)&g_flag[dir][nb]) = 1;
    }
    if (tid < DIRBLK) {
        volatile int* fp = &g_flag[dir][tid];
        while (*fp < 1) {}
        __threadfence();
    }
    __syncthreads();

    // Prefetch x(0) into the x-half of hx.
    {
        const char* xsrc = (const char*)&g_xt[dir][0][0][0];
        #pragma unroll
        for (int j = 0; j < 16; ++j) {
            int i = tid + j * NTHR;
            int k = i >> 4, c = i & 15;
            cpa16(hx_base + (uint32_t)((k * PAD + c * 4) * 4), xsrc + (size_t)i * 16);
        }
        CP_COMMIT();
    }

    // ---------------- recurrence ----------------
    // Thread tile: kq = K-quarter, r -> (bg batch-group of 4, nl local hidden).
    // Epilogue: each thread owns cell (n = nb*4+nl, b = bg*4+kq).
    const int kq = tid >> 6;
    const int r  = tid & 63;
    const int bg = r & 15;
    const int nl = r >> 4;
    const int n  = nb * 4 + nl;
    const int myb = bg * 4 + kq;

    const int   L    = slen[myb];
    float cth = 0.f;
    int p = 0;

    const float* hxp_x = hx  + (kq * 64) * PAD + bg * 4;
    const float* wtp_x = wt2 + (kq * 64) * 32  + nl * 8;
    const float* hxp_h = hx  + (DD + kq * 64) * PAD + bg * 4;
    const float* wtp_h = wt2 + (DD + kq * 64) * 32  + nl * 8;

    for (int s = 0; s < TT; ++s) {
        CP_WAIT0();          // x(s) landed (h group of prev step already drained)
        __syncthreads();

        unsigned long long acc2[8];
        #pragma unroll
        for (int i = 0; i < 8; ++i) acc2[i] = 0ull;

        // ---- x-half: no dependence on h(s); hides skew + flag latency ----
        gemm_phase(acc2, hxp_x, wtp_x);

        // ---- wait for h(s) to be published by all blocks of this dir ----
        if (tid < DIRBLK) {
            volatile int* fp = &g_flag[dir][tid];
            while (*fp < s + 1) {}
            __threadfence();
        }
        __syncthreads();

        // ---- fetch h(s) into the h-half of hx ----
        {
            const char* hsrc = (const char*)&g_hb[dir][p][0][0];
            #pragma unroll
            for (int j = 0; j < 16; ++j) {
                int i = tid + j * NTHR;
                int k = i >> 4, c = i & 15;
                cpa16(hx_base + (uint32_t)(((DD + k) * PAD + c * 4) * 4),
                      hsrc + (size_t)i * 16);
            }
            CP_COMMIT();
            CP_WAIT0();
        }
        __syncthreads();

        // ---- h-half ----
        gemm_phase(acc2, hxp_h, wtp_h);

        // unpack packed partials and publish (all kq groups)
        {
            float accf[16];
            #pragma unroll
            for (int i = 0; i < 8; ++i) {
                int g = i >> 1, bp = i & 1;
                unpack2(acc2[i], accf[g * 4 + bp * 2], accf[g * 4 + bp * 2 + 1]);
            }
            #pragma unroll
            for (int i = 0; i < 16; ++i)
                red[(kq * 16 + i) * 64 + r] = accf[i];
        }
        __syncthreads();   // all warps done with FFMA + hx regions

        // prefetch x(s+1); overlaps epilogue + flag post + next-step skew
        if (s + 1 < TT) {
            const char* xsrc = (const char*)&g_xt[dir][s + 1][0][0];
            #pragma unroll
            for (int j = 0; j < 16; ++j) {
                int i = tid + j * NTHR;
                int k = i >> 4, c = i & 15;
                cpa16(hx_base + (uint32_t)((k * PAD + c * 4) * 4), xsrc + (size_t)i * 16);
            }
            CP_COMMIT();
        }

        // ---- epilogue: 1 cell per thread (gate g row index = g*4 + kq) ----
        float pre[4];
        #pragma unroll
        for (int g = 0; g < 4; ++g) {
            int col = g * 4 + kq;   // (gate g, batch-index kq) within thread-tile
            pre[g] = red[( 0 + (nl * 4 + 0) * 0 + col) * 64 + r]   // kq'=0
                   + red[(16 + col) * 64 + r]                      // kq'=1
                   + red[(32 + col) * 64 + r]                      // kq'=2
                   + red[(48 + col) * 64 + r]                      // kq'=3
                   + bsv[nl * 4 + g];
        }
        float si = fsig(pre[0]);
        float sf = fsig(pre[1]);
        float tg = ftanh(pre[2]);
        float so = fsig(pre[3]);
        cth = sf * cth + si * tg;
        float hval = so * ftanh(cth);

        g_hb[dir][p ^ 1][n][myb] = hval;

        __syncthreads();
        if (tid == 0) {
            __threadfence();
            *((volatile int*)&g_flag[dir][nb]) = s + 2;
        }

        // masked output write (not consumed by other blocks -> off critical path)
        if (s < L) {
            const int t = dir ? (L - 1 - s) : s;
            out[((size_t)myb * TT + t) * (2 * HH) + dir * HH + n] = hval;
        }

        p ^= 1;
    }

    // ---- final local-sense barrier (launch-stable), then reset flags ----
    __syncthreads();
    if (tid == 0) {
        unsigned s0 = *((volatile unsigned*)&g_bsns[dir]);
        __threadfence();
        unsigned a = atomicAdd(&g_bcnt[dir], 1u);
        if (a == DIRBLK - 1) {
            atomicExch(&g_bcnt[dir], 0u);
            __threadfence();
            atomicExch(&g_bsns[dir], s0 ^ 1u);
        } else {
            while (*((volatile unsigned*)&g_bsns[dir]) == s0) {}
        }
        __threadfence();
        *((volatile int*)&g_flag[dir][nb]) = 0;   // pristine for next graph replay
    }
}

extern "C" void kernel_launch(void* const* d_in, const int* in_sizes, int n_in,
                              void* d_out, int out_size) {
    const float* x     = (const float*)d_in[0];
    const int*   lens  = (const int*)  d_in[1];
    const float* Wih_f = (const float*)d_in[2];
    const float* Whh_f = (const float*)d_in[3];
    const float* bih_f = (const float*)d_in[4];
    const float* bhh_f = (const float*)d_in[5];
    const float* Wih_b = (const float*)d_in[6];
    const float* Whh_b = (const float*)d_in[7];
    const float* bih_b = (const float*)d_in[8];
    const float* bhh_b = (const float*)d_in[9];
    float* out = (float*)d_out;

    // zero the padded/masked region (output beyond input_length must be 0)
    cudaMemsetAsync(out, 0, (size_t)out_size * sizeof(float), 0);

    const size_t smem_bytes =
        (size_t)(KK * PAD + KK * 32 + 4 * 16 * 64 + 16) * sizeof(float)
        + BB * sizeof(int);
    cudaFuncSetAttribute(bilstm_kernel,
                         cudaFuncAttributeMaxDynamicSharedMemorySize, (int)smem_bytes);

    bilstm_kernel<<<NBLK, NTHR, smem_bytes>>>(x, lens, Wih_f, Whh_f, bih_f, bhh_f,
                                              Wih_b, Whh_b, bih_b, bhh_b, out);
}

// round 8
// speedup vs baseline: 1.3616x; 1.0578x over previous
#include <cuda_runtime.h>
#include <cstdint>
#include <math.h>

#define BB 64
#define TT 512
#define DD 256
#define HH 256
#define KK 512
#define NTHR 256
#define NBLK 128
#define NB_N 16        // hidden dims per block
#define NB_B 16        // batches per block
#define NGRP 8         // sync groups (dir x bgrp)
#define GRPBLK 16      // blocks per sync group

// ---------------- device scratch (static allocation, allowed) ----------------
__device__ float g_xt[2][TT][4][DD][2 * NB_B];  // [dir][t][bgrp][k][b-dup]   (128 MB)
__device__ float g_hb[2][2][4][HH][2 * NB_B];   // [dir][phase][bgrp][n][b-dup] (1 MB)
__device__ int      g_flag[NGRP][GRPBLK];       // step flags (reset at end)
__device__ unsigned g_bcnt, g_bsns;             // global barrier (self-stable)

// ---- fast gate math (|rel err| ~1e-6, saturation-safe) ----
__device__ __forceinline__ float fsig(float v) {
    return __fdividef(1.f, 1.f + __expf(-v));
}
__device__ __forceinline__ float ftanh(float v) {
    return 1.f - __fdividef(2.f, __expf(2.f * v) + 1.f);
}

// ---- packed fp32x2 helpers (sm_100+) ----
__device__ __forceinline__ void fmaf2(unsigned long long& d,
                                      unsigned long long a, unsigned long long b) {
    asm("fma.rn.f32x2 %0, %1, %2, %3;" : "=l"(d) : "l"(a), "l"(b), "l"(d));
}
__device__ __forceinline__ unsigned long long addf2(unsigned long long a,
                                                    unsigned long long b) {
    unsigned long long r;
    asm("add.rn.f32x2 %0, %1, %2;" : "=l"(r) : "l"(a), "l"(b));
    return r;
}
__device__ __forceinline__ void unpack2(unsigned long long v, float& lo, float& hi) {
    asm("mov.b64 {%0, %1}, %2;" : "=f"(lo), "=f"(hi) : "l"(v));
}

// ---- cp.async helpers ----
__device__ __forceinline__ void cpa16(uint32_t dst_smem, const void* src) {
    asm volatile("cp.async.cg.shared.global [%0], [%1], 16;"
                 :: "r"(dst_smem), "l"(src));
}
#define CP_COMMIT() asm volatile("cp.async.commit_group;")
#define CP_WAIT(n)  asm volatile("cp.async.wait_group %0;" :: "n"(n))

__device__ __forceinline__ uint32_t smem_u32(const void* p) {
    uint32_t a;
    asm("{ .reg .u64 t; cvta.to.shared.u64 t, %1; cvt.u32.u64 %0, t; }"
        : "=r"(a) : "l"(p));
    return a;
}

// Inner GEMM: N k-steps. Per k: w2 = 2 gate-pairs (g0,g1),(g2,g3) of this nl;
// hA/hB = 4 batches duplicated. 8 FFMA2 = 16 MACs.
template <int N>
__device__ __forceinline__ void gemm_phase(unsigned long long* acc2,
                                           const float* __restrict__ hxp,
                                           const float* __restrict__ wtp) {
    #pragma unroll 8
    for (int kk = 0; kk < N; ++kk) {
        ulonglong2 w2 = *(const ulonglong2*)(wtp + kk * 64);       // (g0,g1),(g2,g3)
        ulonglong2 hA = *(const ulonglong2*)(hxp + kk * 32);       // (b0,b0),(b1,b1)
        ulonglong2 hB = *(const ulonglong2*)(hxp + kk * 32 + 4);   // (b2,b2),(b3,b3)
        fmaf2(acc2[0], w2.x, hA.x); fmaf2(acc2[1], w2.x, hA.y);
        fmaf2(acc2[2], w2.x, hB.x); fmaf2(acc2[3], w2.x, hB.y);
        fmaf2(acc2[4], w2.y, hA.x); fmaf2(acc2[5], w2.y, hA.y);
        fmaf2(acc2[6], w2.y, hB.x); fmaf2(acc2[7], w2.y, hB.y);
    }
}

__device__ __forceinline__ void global_barrier(int tid) {
    __syncthreads();
    if (tid == 0) {
        unsigned s0 = *((volatile unsigned*)&g_bsns);
        __threadfence();
        unsigned a = atomicAdd(&g_bcnt, 1u);
        if (a == NBLK - 1) {
            atomicExch(&g_bcnt, 0u);
            __threadfence();
            atomicExch(&g_bsns, s0 ^ 1u);
        } else {
            while (*((volatile unsigned*)&g_bsns) == s0) {}
        }
        __threadfence();
    }
    __syncthreads();
}

extern "C" __global__ void __launch_bounds__(NTHR, 1)
bilstm_kernel(const float* __restrict__ x,
              const int*   __restrict__ lens,
              const float* __restrict__ Wih_f, const float* __restrict__ Whh_f,
              const float* __restrict__ bih_f, const float* __restrict__ bhh_f,
              const float* __restrict__ Wih_b, const float* __restrict__ Whh_b,
              const float* __restrict__ bih_b, const float* __restrict__ bhh_b,
              float* __restrict__ out)
{
    extern __shared__ float smem[];
    float* hx  = smem;                          // [512][32]  [x_t ; h] batch-dup
    float* wt  = hx + KK * 32;                  // [512][64]  weight rows (gate pairs)
    unsigned long long* red =
        (unsigned long long*)(wt + KK * 64);    // [4][16][2][16] kq-split partials
    float* bsv  = (float*)(red + 4 * 16 * 2 * 16);  // [64] bih+bhh
    int*   slen = (int*)(bsv + 64);             // [64]
    float* tile = wt;                           // prologue transpose tile [256][65]

    const uint32_t hx_base = smem_u32(hx);

    const int tid  = threadIdx.x;
    const int dir  = blockIdx.x >> 6;
    const int bgrp = (blockIdx.x >> 4) & 3;     // 16-batch group
    const int nc   = blockIdx.x & 15;           // 16-hidden-dim chunk
    const int gid  = blockIdx.x >> 4;           // sync group 0..7

    const float* Wih = dir ? Wih_b : Wih_f;
    const float* Whh = dir ? Whh_b : Whh_f;
    const float* bih = dir ? bih_b : bih_f;
    const float* bhh = dir ? bhh_b : bhh_f;

    // ---------------- prologue ----------------
    if (tid < BB) slen[tid] = lens[tid];
    __syncthreads();

    // x transpose+dup via smem tile (per-dir, blocks idx64 stride 64 over t)
    {
        const int idx64 = blockIdx.x & 63;
        const int bq  = tid >> 2;               // batch 0..63
        const int kq4 = tid & 3;                // k quarter 0..3
        for (int s = idx64; s < TT; s += 64) {
            int t;
            if (dir == 0) t = s;
            else          t = TT - 1 - ((TT - slen[bq] + s) % TT);
            const float* xrow = x + ((size_t)bq * TT + t) * DD;
            #pragma unroll
            for (int kk = 0; kk < 16; ++kk) {
                int k0 = kq4 * 64 + kk * 4;
                float4 v = *(const float4*)(xrow + k0);
                tile[(k0 + 0) * 65 + bq] = v.x;
                tile[(k0 + 1) * 65 + bq] = v.y;
                tile[(k0 + 2) * 65 + bq] = v.z;
                tile[(k0 + 3) * 65 + bq] = v.w;
            }
            __syncthreads();
            // write out duplicated, coalesced
            const int k2 = tid;                 // 0..255
            #pragma unroll
            for (int bg4 = 0; bg4 < 4; ++bg4) {
                float* dst = &g_xt[dir][s][bg4][k2][0];
                #pragma unroll
                for (int blp = 0; blp < 8; ++blp) {
                    float f0 = tile[k2 * 65 + bg4 * 16 + blp * 2 + 0];
                    float f1 = tile[k2 * 65 + bg4 * 16 + blp * 2 + 1];
                    float4 w; w.x = f0; w.y = f0; w.z = f1; w.w = f1;
                    *(float4*)(dst + blp * 4) = w;
                }
            }
            __syncthreads();
        }
    }

    // weight slice: wt[k][r], r = nl*4 + g (gate order i,f,g,o), rows for nc
    for (int idx = tid; idx < KK * 64; idx += NTHR) {
        int k = idx >> 6, r = idx & 63;
        int nl = r >> 2, g = r & 3;
        int j = g * HH + nc * NB_N + nl;
        wt[idx] = (k < DD) ? Wih[(size_t)j * DD + k] : Whh[(size_t)j * HH + (k - DD)];
    }
    if (tid < 64) {
        int nl = tid >> 2, g = tid & 3;
        int j = g * HH + nc * NB_N + nl;
        bsv[tid] = bih[j] + bhh[j];
    }
    // zero all h buffers (cooperative across all blocks)
    {
        float* hb = &g_hb[0][0][0][0][0];
        const int total = 2 * 2 * 4 * HH * 2 * NB_B;
        for (int i = blockIdx.x * NTHR + tid; i < total; i += NBLK * NTHR) hb[i] = 0.f;
    }
    __syncthreads();
    if (tid == 0) *((volatile int*)&g_flag[gid][nc]) = 1;   // h(0) ready

    global_barrier(tid);

    // prefetch x(0) -> hx x-half (layouts match: contiguous copy)
    {
        const char* xsrc = (const char*)&g_xt[dir][0][bgrp][0][0];
        #pragma unroll
        for (int j = 0; j < 8; ++j) {
            int i = tid + j * NTHR;             // 0..2047 chunks of 16B
            cpa16(hx_base + (uint32_t)(i * 16), xsrc + (size_t)i * 16);
        }
        CP_COMMIT();
    }

    // ---------------- recurrence ----------------
    // GEMM map: kq = K quarter, nl = local hidden (4 gate rows), bgq = 4 batches
    const int kq  = tid >> 6;
    const int r6  = tid & 63;
    const int nl  = r6 >> 2;
    const int bgq = r6 & 3;
    // epilogue map: one (n, b) cell per thread
    const int nl2 = tid >> 4;
    const int bl  = tid & 15;
    const int n   = nc * NB_N + nl2;
    const int myb = bgrp * NB_B + bl;
    const int L   = slen[myb];

    const float* hxp_x  = hx + (kq * 64) * 32 + bgq * 8;
    const float* wtp_x  = wt + (kq * 64) * 64 + nl * 4;
    const float* hxp_hA = hx + (DD + kq * 64) * 32 + bgq * 8;
    const float* wtp_hA = wt + (DD + kq * 64) * 64 + nl * 4;

    float cth = 0.f;
    int p = 0;

    for (int s = 0; s < TT; ++s) {
        CP_WAIT(0);                 // x(s) landed
        __syncthreads();

        unsigned long long acc2[8];
        #pragma unroll
        for (int i = 0; i < 8; ++i) acc2[i] = 0ull;

        // x-half (K=256): independent of h(s); hides skew + flag latency
        gemm_phase<64>(acc2, hxp_x, wtp_x);

        // wait for h(s) from the 16 blocks of this group
        if (tid < GRPBLK) {
            volatile int* fp = &g_flag[gid][tid];
            while (*fp < s + 1) {}
            __threadfence();
        }
        __syncthreads();

        // fetch h(s) in two k-interleaved commit groups (pipelined with gemm)
        {
            const char* hsrc = (const char*)&g_hb[dir][p][bgrp][0][0];
            const uint32_t hdst = hx_base + (uint32_t)(DD * 32 * 4);
            #pragma unroll
            for (int j = 0; j < 4; ++j) {       // group A: kk with (kk & 32)==0
                int a = tid + j * NTHR;         // 0..1023
                int i = (a & 255) + ((a >> 8) << 9);
                cpa16(hdst + (uint32_t)(i * 16), hsrc + (size_t)i * 16);
            }
            CP_COMMIT();
            #pragma unroll
            for (int j = 0; j < 4; ++j) {       // group B: kk with (kk & 32)==32
                int a = tid + j * NTHR;
                int i = 256 + (a & 255) + ((a >> 8) << 9);
                cpa16(hdst + (uint32_t)(i * 16), hsrc + (size_t)i * 16);
            }
            CP_COMMIT();
        }
        CP_WAIT(1);                 // group A in
        __syncthreads();
        gemm_phase<32>(acc2, hxp_hA, wtp_hA);
        CP_WAIT(0);                 // group B in
        __syncthreads();
        gemm_phase<32>(acc2, hxp_hA + 32 * 32, wtp_hA + 32 * 64);

        // publish kq-split packed partials: red[kq][nl][pr][b16]
        #pragma unroll
        for (int pr = 0; pr < 2; ++pr)
            #pragma unroll
            for (int bi = 0; bi < 4; ++bi)
                red[(((kq * 16 + nl) * 2 + pr) * 16) + bgq * 4 + bi] = acc2[pr * 4 + bi];
        __syncthreads();

        // prefetch x(s+1): overlaps epilogue + flag post + next-step skew
        if (s + 1 < TT) {
            const char* xsrc = (const char*)&g_xt[dir][s + 1][bgrp][0][0];
            #pragma unroll
            for (int j = 0; j < 8; ++j) {
                int i = tid + j * NTHR;
                cpa16(hx_base + (uint32_t)(i * 16), xsrc + (size_t)i * 16);
            }
            CP_COMMIT();
        }

        // epilogue: reduce 4 kq, gates, cell update  (1 cell per thread)
        {
            unsigned long long s01 =
                addf2(addf2(red[((0 * 16 + nl2) * 2 + 0) * 16 + bl],
                            red[((1 * 16 + nl2) * 2 + 0) * 16 + bl]),
                      addf2(red[((2 * 16 + nl2) * 2 + 0) * 16 + bl],
                            red[((3 * 16 + nl2) * 2 + 0) * 16 + bl]));
            unsigned long long s23 =
                addf2(addf2(red[((0 * 16 + nl2) * 2 + 1) * 16 + bl],
                            red[((1 * 16 + nl2) * 2 + 1) * 16 + bl]),
                      addf2(red[((2 * 16 + nl2) * 2 + 1) * 16 + bl],
                            red[((3 * 16 + nl2) * 2 + 1) * 16 + bl]));
            float pi, pf, pg, po;
            unpack2(s01, pi, pf);
            unpack2(s23, pg, po);
            pi += bsv[nl2 * 4 + 0];
            pf += bsv[nl2 * 4 + 1];
            pg += bsv[nl2 * 4 + 2];
            po += bsv[nl2 * 4 + 3];

            float si = fsig(pi), sf = fsig(pf), tg = ftanh(pg), so = fsig(po);
            cth = sf * cth + si * tg;
            float hval = so * ftanh(cth);

            float2 hd; hd.x = hval; hd.y = hval;
            *(float2*)&g_hb[dir][p ^ 1][bgrp][n][bl * 2] = hd;

            __syncthreads();
            if (tid == 0) {
                __threadfence();
                *((volatile int*)&g_flag[gid][nc]) = s + 2;
            }

            if (s < L) {
                const int t = dir ? (L - 1 - s) : s;
                out[((size_t)myb * TT + t) * (2 * HH) + dir * HH + n] = hval;
            }
        }
        p ^= 1;
    }

    // final barrier, then reset flags for the next graph replay
    global_barrier(tid);
    if (tid == 0) *((volatile int*)&g_flag[gid][nc]) = 0;
}

extern "C" void kernel_launch(void* const* d_in, const int* in_sizes, int n_in,
                              void* d_out, int out_size) {
    const float* x     = (const float*)d_in[0];
    const int*   lens  = (const int*)  d_in[1];
    const float* Wih_f = (const float*)d_in[2];
    const float* Whh_f = (const float*)d_in[3];
    const float* bih_f = (const float*)d_in[4];
    const float* bhh_f = (const float*)d_in[5];
    const float* Wih_b = (const float*)d_in[6];
    const float* Whh_b = (const float*)d_in[7];
    const float* bih_b = (const float*)d_in[8];
    const float* bhh_b = (const float*)d_in[9];
    float* out = (float*)d_out;

    // zero the padded/masked region (output beyond input_length must be 0)
    cudaMemsetAsync(out, 0, (size_t)out_size * sizeof(float), 0);

    const size_t smem_bytes =
        (size_t)(KK * 32 + KK * 64) * sizeof(float)        // hx + wt
        + (size_t)(4 * 16 * 2 * 16) * sizeof(unsigned long long)  // red
        + 64 * sizeof(float) + 64 * sizeof(int);           // bsv + slen
    cudaFuncSetAttribute(bilstm_kernel,
                         cudaFuncAttributeMaxDynamicSharedMemorySize, (int)smem_bytes);

    bilstm_kernel<<<NBLK, NTHR, smem_bytes>>>(x, lens, Wih_f, Whh_f, bih_f, bhh_f,
                                              Wih_b, Whh_b, bih_b, bhh_b, out);
}